// round 16
// baseline (speedup 1.0000x reference)
#include <cuda_runtime.h>
#include <cuda_bf16.h>

// BSplineBasis, uniform knots, truncated-power form (R7 math — proven fastest),
// with float4-vectorized global I/O: each thread owns 4 adjacent splines, so
// STG.128 (12 issue slots / 4 elems) replaces 4x STG.32 (5 each), and LDG +
// address arithmetic amortize 4x. Math per element unchanged.
// x: (4096,4096) f32, coefficients: (4096,8) f32, grid: (12,) f32 uniform.

#define S_TOTAL 4096
#define B_TOTAL 4096
#define THREADS 128
#define SPT     4
#define TILE_S  (THREADS * SPT)       // 512 splines/block
#define GRID_X  (S_TOTAL / TILE_S)    // 8
#define GRID_Y  256
#define ROWS    (B_TOTAL / GRID_Y)    // 16
#define UN      4                     // float4-rows in flight (16 elems)

__global__ __launch_bounds__(THREADS, 8)
void bspline_kernel(const float* __restrict__ x,
                    const float* __restrict__ coeff,
                    const float* __restrict__ grid,
                    float* __restrict__ out)
{
    const int t  = threadIdx.x;
    const int s0 = blockIdx.x * TILE_S + t * SPT;

    // ---- Truncated-power tables for 4 adjacent splines (32 regs) ----
    float A[SPT], B[SPT], C[SPT], D[SPT], E1[SPT], E2[SPT], E3[SPT], E4[SPT];
    #pragma unroll
    for (int j = 0; j < SPT; j++) {
        const float4* crow = reinterpret_cast<const float4*>(coeff + (size_t)(s0 + j) * 8);
        float4 qa = crow[0], qb = crow[1];
        float c8[8] = {qa.x, qa.y, qa.z, qa.w, qb.x, qb.y, qb.z, qb.w};
        float pd[5];
        #pragma unroll
        for (int w = 0; w < 5; w++)
            pd[w] = (c8[w+3] - c8[w] + 3.0f * (c8[w+1] - c8[w+2])) * (1.0f / 6.0f);
        A[j]  = (c8[0] + 4.0f * c8[1] + c8[2]) * (1.0f / 6.0f);
        B[j]  = (c8[2] - c8[0]) * 0.5f;
        C[j]  = (c8[0] - 2.0f * c8[1] + c8[2]) * 0.5f;
        D[j]  = pd[0];
        E1[j] = pd[1] - pd[0];
        E2[j] = pd[2] - pd[1];
        E3[j] = pd[3] - pd[2];
        E4[j] = pd[4] - pd[3];
    }

    const float gstart = __ldg(&grid[3]);
    const float invh   = 1.0f / (__ldg(&grid[1]) - __ldg(&grid[0]));
    const float c0     = -gstart * invh;              // y = x*invh + c0, in [0,5)

    const int b0 = blockIdx.y * ROWS;
    const float* xp = x   + (size_t)b0 * S_TOTAL + s0;
    float*       op = out + (size_t)b0 * S_TOTAL + s0;

    #pragma unroll 1
    for (int r = 0; r < ROWS; r += UN) {
        float4 xv[UN];
        #pragma unroll
        for (int k = 0; k < UN; k++)
            xv[k] = *reinterpret_cast<const float4*>(xp + (size_t)k * S_TOTAL);

        #pragma unroll
        for (int k = 0; k < UN; k++) {
            float xi[SPT] = {xv[k].x, xv[k].y, xv[k].z, xv[k].w};
            float vo[SPT];
            #pragma unroll
            for (int j = 0; j < SPT; j++) {
                float y = fmaf(xi[j], invh, c0);
                float v = fmaf(fmaf(fmaf(D[j], y, C[j]), y, B[j]), y, A[j]);
                float r1 = fmaxf(y - 1.0f, 0.0f);
                float r2 = fmaxf(y - 2.0f, 0.0f);
                float r3 = fmaxf(y - 3.0f, 0.0f);
                float r4 = fmaxf(y - 4.0f, 0.0f);
                v = fmaf(E1[j], r1 * r1 * r1, v);
                v = fmaf(E2[j], r2 * r2 * r2, v);
                v = fmaf(E3[j], r3 * r3 * r3, v);
                v = fmaf(E4[j], r4 * r4 * r4, v);
                vo[j] = v;
            }
            *reinterpret_cast<float4*>(op + (size_t)k * S_TOTAL) =
                make_float4(vo[0], vo[1], vo[2], vo[3]);
        }
        xp += (size_t)UN * S_TOTAL;
        op += (size_t)UN * S_TOTAL;
    }
}

extern "C" void kernel_launch(void* const* d_in, const int* in_sizes, int n_in,
                              void* d_out, int out_size)
{
    const float* x     = (const float*)d_in[0];
    const float* coeff = (const float*)d_in[1];
    const float* grid  = (const float*)d_in[2];
    float*       out   = (float*)d_out;

    dim3 g(GRID_X, GRID_Y);   // (8, 256) = 2048 blocks
    bspline_kernel<<<g, THREADS>>>(x, coeff, grid, out);
}